// round 11
// baseline (speedup 1.0000x reference)
#include <cuda_runtime.h>
#include <cuda_fp16.h>
#include <cstdint>

#define BATCH 16384
#define DMODEL 1024
#define ODIM 572
#define ODIM_PAD 576

#define BM 128
#define BN 64
#define BK 32
#define KT (DMODEL / BK)
#define NB (ODIM_PAD / BN)   // 9 n-blocks
#define SSTRIDE 40  // 32 + 8 pad: 80B rows -> conflict-free ldmatrix, 16B-aligned

// ---------------- scratch (device globals; no allocation) ----------------
__device__ __half g_Ah[BATCH * DMODEL];              // A rounded once to fp16
__device__ __half g_WhT[ODIM_PAD * DMODEL];          // [n][k] transposed, padded, fp16
__device__ float g_pre[BATCH * ODIM];
__device__ float g_pt[BATCH * NB];                   // per (row, nblk) best t
__device__ int   g_pj[BATCH * NB];                   // per (row, nblk) best col

// ---------------- Threefry-2x32, key = PRNGKey(42) = (0, 42) ----------------
__device__ __forceinline__ uint32_t rotl32(uint32_t v, int d) {
    return __funnelshift_l(v, v, d);
}

__device__ __forceinline__ void threefry_0_42(uint32_t c0, uint32_t c1,
                                              uint32_t& o0, uint32_t& o1) {
    const uint32_t K0 = 0u, K1 = 42u, K2 = 0u ^ 42u ^ 0x1BD11BDAu;
    uint32_t x0 = c0 + K0;
    uint32_t x1 = c1 + K1;
#define RND(r) { x0 += x1; x1 = rotl32(x1, r) ^ x0; }
    RND(13) RND(15) RND(26) RND(6)
    x0 += K1; x1 += K2 + 1u;
    RND(17) RND(29) RND(16) RND(24)
    x0 += K2; x1 += K0 + 2u;
    RND(13) RND(15) RND(26) RND(6)
    x0 += K0; x1 += K1 + 3u;
    RND(17) RND(29) RND(16) RND(24)
    x0 += K1; x1 += K2 + 4u;
    RND(13) RND(15) RND(26) RND(6)
    x0 += K2; x1 += K0 + 5u;
#undef RND
    o0 = x0; o1 = x1;
}

// JAX threefry_partitionable random_bits, bit_width=32:
//   counter words (0, elem); 32-bit output = bits1 ^ bits2
__device__ __forceinline__ float gumbel_at(uint32_t elem) {
    uint32_t o0, o1;
    threefry_0_42(0u, elem, o0, o1);
    uint32_t bits = o0 ^ o1;
    const float TINY = 1.17549435e-38f;
    float f = __uint_as_float((bits >> 9) | 0x3F800000u) - 1.0f;  // [0,1)
    float u = fmaxf(TINY, f + TINY);
    return -__logf(-__logf(u));
}

// ---------------- convert A: fp32 -> fp16 (vectorized) ----------------
__global__ void convert_a_kernel(const float* __restrict__ A) {
    int stride = gridDim.x * blockDim.x;
    const float2* A2 = (const float2*)A;
    __half2* out2 = (__half2*)g_Ah;
    for (int i = blockIdx.x * blockDim.x + threadIdx.x; i < BATCH * DMODEL / 2; i += stride) {
        float2 a = A2[i];
        out2[i] = __floats2half2_rn(a.x, a.y);
    }
}

// ---------------- convert W1: transpose + pad + fp16 ----------------
__global__ void convert_w_kernel(const float* __restrict__ W1) {
    int stride = gridDim.x * blockDim.x;
    for (int i = blockIdx.x * blockDim.x + threadIdx.x; i < ODIM_PAD * DMODEL; i += stride) {
        int n = i >> 10;          // DMODEL = 1024
        int k = i & 1023;
        float w = (n < ODIM) ? __ldg(&W1[k * ODIM + n]) : 0.0f;
        g_WhT[i] = __float2half(w);   // i == n*1024 + k
    }
}

// ---------------- GEMM + gumbel-argmax partials ----------------
#define MMA_F16(C, A, B)                                                      \
    asm volatile(                                                             \
        "mma.sync.aligned.m16n8k16.row.col.f32.f16.f16.f32 "                  \
        "{%0,%1,%2,%3}, {%4,%5,%6,%7}, {%8,%9}, {%0,%1,%2,%3};"               \
        : "+f"(C[0]), "+f"(C[1]), "+f"(C[2]), "+f"(C[3])                      \
        : "r"((A)[0]), "r"((A)[1]), "r"((A)[2]), "r"((A)[3]),                 \
          "r"((B)[0]), "r"((B)[1]))

#define LDSM4(R, addr)                                                        \
    asm volatile("ldmatrix.sync.aligned.m8n8.x4.shared.b16 {%0,%1,%2,%3}, [%4];" \
        : "=r"((R)[0]), "=r"((R)[1]), "=r"((R)[2]), "=r"((R)[3]) : "r"(addr))

__global__ __launch_bounds__(256) void gemm_kernel(const float* __restrict__ b1) {
    __shared__ __align__(16) __half sA[3][BM][SSTRIDE];     // 30720 B
    __shared__ __align__(16) __half sW[3][BN][SSTRIDE];     // 15360 B
    __shared__ float s_pt[2][BM];                           // 1024 B
    __shared__ int   s_pj[2][BM];                           // 1024 B

    const int m_blk = blockIdx.y * BM;
    const int n_blk = blockIdx.x * BN;

    const int lane = threadIdx.x & 31;
    const int warp = threadIdx.x >> 5;     // 0..7
    const int wm = (warp & 3) * 32;        // 4 warps along M
    const int wn = (warp >> 2) * 32;       // 2 warps along N
    const int g = lane >> 2;   // 0..7
    const int tq = lane & 3;   // 0..3

    const int aRow = lane & 15;
    const int aCol = (lane & 16) >> 1;
    const int bRow = (lane & 7) + ((lane & 16) >> 1);
    const int bCol = lane & 8;

    float acc[2][4][4];
#pragma unroll
    for (int a = 0; a < 2; a++)
#pragma unroll
        for (int b = 0; b < 4; b++)
#pragma unroll
            for (int c = 0; c < 4; c++) acc[a][b][c] = 0.0f;

    auto load_stage = [&](int s, int kt) {
        int k0 = kt * BK;
        for (int id = threadIdx.x; id < 768; id += 256) {
            const __half* src;
            __half* dst;
            if (id < 512) {
                int r = id >> 2, col = (id & 3) * 8;
                src = g_Ah + (size_t)(m_blk + r) * DMODEL + k0 + col;
                dst = &sA[s][r][col];
            } else {
                int c = id - 512;
                int r = c >> 2, col = (c & 3) * 8;
                src = g_WhT + (size_t)(n_blk + r) * DMODEL + k0 + col;
                dst = &sW[s][r][col];
            }
            unsigned sa = (unsigned)__cvta_generic_to_shared(dst);
            asm volatile("cp.async.cg.shared.global [%0], [%1], 16;" :: "r"(sa), "l"(src));
        }
        asm volatile("cp.async.commit_group;");
    };

    load_stage(0, 0);
    load_stage(1, 1);

    for (int kt = 0; kt < KT; kt++) {
        const int s = kt % 3;
        if (kt + 1 < KT) asm volatile("cp.async.wait_group 1;");
        else             asm volatile("cp.async.wait_group 0;");
        __syncthreads();
        if (kt + 2 < KT) load_stage((kt + 2) % 3, kt + 2);

#pragma unroll
        for (int ks = 0; ks < 2; ks++) {
            const int kk = ks * 16;
            uint32_t af[2][4];
            uint32_t bf[2][4];
#pragma unroll
            for (int fm = 0; fm < 2; fm++) {
                unsigned pa = (unsigned)__cvta_generic_to_shared(
                    &sA[s][wm + fm * 16 + aRow][kk + aCol]);
                LDSM4(af[fm], pa);
            }
#pragma unroll
            for (int fb = 0; fb < 2; fb++) {
                unsigned pb = (unsigned)__cvta_generic_to_shared(
                    &sW[s][wn + fb * 16 + bRow][kk + bCol]);
                LDSM4(bf[fb], pb);
            }
#pragma unroll
            for (int fm = 0; fm < 2; fm++)
#pragma unroll
                for (int fn = 0; fn < 4; fn++) {
                    const uint32_t* B = &bf[fn >> 1][(fn & 1) * 2];
                    MMA_F16(acc[fm][fn], af[fm], B);
                }
        }
    }

    // ---- output phase: bias add, g_pre store, gumbel-argmax partials ----
    float bt[2][2] = {{-3.4e38f, -3.4e38f}, {-3.4e38f, -3.4e38f}};
    int bj[2][2] = {{ODIM, ODIM}, {ODIM, ODIM}};

#pragma unroll
    for (int fm = 0; fm < 2; fm++) {
        const int row0 = m_blk + wm + fm * 16 + g;
#pragma unroll
        for (int fn = 0; fn < 4; fn++) {
            const int col = n_blk + wn + fn * 8 + tq * 2;
#pragma unroll
            for (int e = 0; e < 2; e++) {       // col, col+1 (ascending: ties keep lowest)
                const int c = col + e;
                if (c < ODIM) {
                    const float bb = __ldg(&b1[c]);
                    const float v0 = acc[fm][fn][e] + bb;       // (row0,   c)
                    const float v1 = acc[fm][fn][e + 2] + bb;   // (row0+8, c)
                    g_pre[(size_t)row0 * ODIM + c] = v0;
                    g_pre[(size_t)(row0 + 8) * ODIM + c] = v1;
                    const float t0 = v0 + gumbel_at((uint32_t)(row0 * ODIM + c));
                    const float t1 = v1 + gumbel_at((uint32_t)((row0 + 8) * ODIM + c));
                    if (t0 > bt[fm][0]) { bt[fm][0] = t0; bj[fm][0] = c; }
                    if (t1 > bt[fm][1]) { bt[fm][1] = t1; bj[fm][1] = c; }
                }
            }
        }
    }

    // quad reduce across tq (lane bits 0-1); ties -> lower col
#pragma unroll
    for (int m = 1; m <= 2; m <<= 1) {
#pragma unroll
        for (int fm = 0; fm < 2; fm++)
#pragma unroll
            for (int h = 0; h < 2; h++) {
                float ot = __shfl_xor_sync(0xffffffffu, bt[fm][h], m);
                int oj = __shfl_xor_sync(0xffffffffu, bj[fm][h], m);
                if (ot > bt[fm][h] || (ot == bt[fm][h] && oj < bj[fm][h])) {
                    bt[fm][h] = ot; bj[fm][h] = oj;
                }
            }
    }

    __syncthreads();   // mainloop smem no longer needed; also orders s_pt reuse
    const int nw = warp >> 2;
    if (tq == 0) {
#pragma unroll
        for (int fm = 0; fm < 2; fm++)
#pragma unroll
            for (int h = 0; h < 2; h++) {
                int rl = wm + fm * 16 + h * 8 + g;
                s_pt[nw][rl] = bt[fm][h];
                s_pj[nw][rl] = bj[fm][h];
            }
    }
    __syncthreads();

    if (threadIdx.x < BM) {
        float t0 = s_pt[0][threadIdx.x], t1 = s_pt[1][threadIdx.x];
        int j0 = s_pj[0][threadIdx.x], j1 = s_pj[1][threadIdx.x];
        float T; int J;
        if (t1 > t0 || (t1 == t0 && j1 < j0)) { T = t1; J = j1; }
        else { T = t0; J = j0; }
        const int grow = m_blk + threadIdx.x;
        g_pt[grow * NB + blockIdx.x] = T;
        g_pj[grow * NB + blockIdx.x] = J;
    }
}

// ---------------- fused softmax + sample-combine + gather + residual ----------------
__global__ __launch_bounds__(128) void epilogue_kernel(
    const float* __restrict__ core, const float* __restrict__ W2,
    const float* __restrict__ b2, float* __restrict__ out) {
    const int row = blockIdx.x;
    const int tid = threadIdx.x;
    const float* pre = g_pre + (size_t)row * ODIM;

    __shared__ float s_max[4];
    __shared__ float s_sum[4];
    __shared__ int s_idx;

    // combine the 9 per-block argmax partials (ascending block -> lowest col on ties)
    if (tid == 0) {
        float bt = -3.4e38f; int bj = ODIM;
#pragma unroll
        for (int b = 0; b < NB; b++) {
            float t = g_pt[row * NB + b];
            int j = g_pj[row * NB + b];
            if (t > bt || (t == bt && j < bj)) { bt = t; bj = j; }
        }
        s_idx = bj;
    }

    float v[5];
    float lmax = -3.4e38f;
#pragma unroll
    for (int jj = 0; jj < 5; jj++) {
        int j = tid + jj * 128;
        if (j < ODIM) {
            float x = pre[j];
            v[jj] = x;
            lmax = fmaxf(lmax, x);
        }
    }
#pragma unroll
    for (int o = 16; o > 0; o >>= 1)
        lmax = fmaxf(lmax, __shfl_xor_sync(0xffffffffu, lmax, o));
    if ((tid & 31) == 0) s_max[tid >> 5] = lmax;
    __syncthreads();
    float rmax = fmaxf(fmaxf(s_max[0], s_max[1]), fmaxf(s_max[2], s_max[3]));

    float e[5];
    float lsum = 0.0f;
#pragma unroll
    for (int jj = 0; jj < 5; jj++) {
        int j = tid + jj * 128;
        if (j < ODIM) {
            e[jj] = __expf(v[jj] - rmax);
            lsum += e[jj];
        }
    }
#pragma unroll
    for (int o = 16; o > 0; o >>= 1) lsum += __shfl_xor_sync(0xffffffffu, lsum, o);
    if ((tid & 31) == 0) s_sum[tid >> 5] = lsum;
    __syncthreads();
    float tot = (s_sum[0] + s_sum[1]) + (s_sum[2] + s_sum[3]);
    float inv = 1.0f / tot;

    float* probs = out + (size_t)row * ODIM;
#pragma unroll
    for (int jj = 0; jj < 5; jj++) {
        int j = tid + jj * 128;
        if (j < ODIM) probs[j] = e[jj] * inv;
    }

    const int idx = s_idx;   // visible: __syncthreads() above happened after the tid==0 write
    const float* w2r = W2 + (size_t)idx * DMODEL;
    const float* cr = core + (size_t)row * DMODEL;
    float* emb = out + (size_t)BATCH * ODIM + (size_t)row * DMODEL;
#pragma unroll
    for (int jj = 0; jj < 8; jj++) {
        int j = tid + jj * 128;
        float h = __ldg(&w2r[j]) + b2[j];
        emb[j] = fmaxf(h, 0.0f) + cr[j];
    }
}

// ---------------- launch ----------------
extern "C" void kernel_launch(void* const* d_in, const int* in_sizes, int n_in,
                              void* d_out, int out_size) {
    const float* core = (const float*)d_in[0];
    const float* W1   = (const float*)d_in[1];
    const float* b1   = (const float*)d_in[2];
    const float* W2   = (const float*)d_in[3];
    const float* b2   = (const float*)d_in[4];
    float* out = (float*)d_out;

    convert_a_kernel<<<2048, 256>>>(core);
    convert_w_kernel<<<288, 256>>>(W1);
    gemm_kernel<<<dim3(NB, BATCH / BM), 256>>>(b1);
    epilogue_kernel<<<BATCH, 128>>>(core, W2, b2, out);
}